// round 4
// baseline (speedup 1.0000x reference)
#include <cuda_runtime.h>
#include <cstdint>

#define BB 128
#define TT 4096
#define KK 64
#define CHUNK 64
#define NCH   (TT / CHUNK)   /* 64 chunks */
#define GRP   8              /* chunks walked per group (32 KB smem) */

// scratch: 32 MB backpointer store (static __device__: allocation-free)
__device__ __align__(16) uint8_t g_bp[(size_t)BB * TT * KK];

// =====================================================================
// ONE kernel does everything for one batch: forward Viterbi (bp staged
// to global per 64-step chunk), then serial in-CTA backward through
// shared-memory reloads, then tag writes (AS FLOAT32), then lengths.
// Exact fp32, first-index argmax (matches jnp.argmax).
// 128 threads = 64 k-columns x 2 predecessor-halves.
// =====================================================================
__global__ __launch_bounds__(128) void crf_kernel(const float* __restrict__ pot,
                                                  const float* __restrict__ trans,
                                                  const int*   __restrict__ mask,
                                                  float*       __restrict__ out) {
    const int b   = blockIdx.x;
    const int tid = threadIdx.x;
    const int k   = tid >> 1;   // 0..63
    const int jh  = tid & 1;    // 0..1

    __shared__ __align__(16) float   st_s[2][KK];            // state double buffer
    __shared__ __align__(16) uint8_t bps[CHUNK][KK];         // bp staging (4 KB)
    __shared__ __align__(16) uint8_t wb[GRP][CHUNK][KK];     // walk buffer (32 KB)
    __shared__ __align__(16) float   tagseg[GRP * CHUNK];    // 512 tags (2 KB)
    __shared__ int scur;                                     // running tag in backward

    // transition slice in registers: tr[i] = transitions[32*jh + i][k]
    float tr[32];
#pragma unroll
    for (int i = 0; i < 32; ++i) tr[i] = trans[(jh * 32 + i) * KK + k];

    const float* pb = pot + (size_t)b * TT * KK;
    uint8_t* bpb = g_bp + (size_t)b * TT * KK;

    if (jh == 0) {
        st_s[0][k] = pb[k];          // alpha_0
        bps[0][k]  = (uint8_t)k;     // row-0 placeholder (never applied)
    }
    __syncthreads();

    // ---------------- forward ----------------
    for (int t = 1; t < TT; ++t) {
        const float* s = st_s[(t - 1) & 1] + jh * 32;
        float emit = pb[(size_t)t * KK + k];

        float v[32];
#pragma unroll
        for (int i = 0; i < 8; ++i) {
            float4 s4 = ((const float4*)s)[i];
            v[4 * i + 0] = s4.x + tr[4 * i + 0];
            v[4 * i + 1] = s4.y + tr[4 * i + 1];
            v[4 * i + 2] = s4.z + tr[4 * i + 2];
            v[4 * i + 3] = s4.w + tr[4 * i + 3];
        }

        // 4 strict-'>' chains of 8 (ascending j => first-index ties), ordered merge
        float bv0 = v[0],  bv1 = v[8],  bv2 = v[16], bv3 = v[24];
        int   bi0 = 0,     bi1 = 8,     bi2 = 16,    bi3 = 24;
#pragma unroll
        for (int i = 1; i < 8; ++i) {
            if (v[i]      > bv0) { bv0 = v[i];      bi0 = i;      }
            if (v[8 + i]  > bv1) { bv1 = v[8 + i];  bi1 = 8 + i;  }
            if (v[16 + i] > bv2) { bv2 = v[16 + i]; bi2 = 16 + i; }
            if (v[24 + i] > bv3) { bv3 = v[24 + i]; bi3 = 24 + i; }
        }
        if (bv1 > bv0) { bv0 = bv1; bi0 = bi1; }
        if (bv2 > bv0) { bv0 = bv2; bi0 = bi2; }
        if (bv3 > bv0) { bv0 = bv3; bi0 = bi3; }

        float best = bv0;
        int   gj   = jh * 32 + bi0;

        // merge the two halves (adjacent lanes); exact first-index tie rule
        float po = __shfl_xor_sync(0xffffffffu, best, 1);
        int   jo = __shfl_xor_sync(0xffffffffu, gj,   1);
        if ((po > best) || ((po == best) && (jo < gj))) { best = po; gj = jo; }

        if (jh == 0) {
            st_s[t & 1][k]          = best + emit;
            bps[t & (CHUNK - 1)][k] = (uint8_t)gj;
        }

        if ((t & (CHUNK - 1)) == (CHUNK - 1)) {
            __syncthreads();   // staging complete
            uint4*       dst = (uint4*)(bpb + (size_t)(t - (CHUNK - 1)) * KK);
            const uint4* src = (const uint4*)bps;
            dst[tid]       = src[tid];
            dst[tid + 128] = src[tid + 128];
        }
        __syncthreads();
    }

    // ---------------- last tag ----------------
    if (tid == 0) {
        const float* fin = st_s[(TT - 1) & 1];
        float bv = fin[0]; int bk = 0;
#pragma unroll
        for (int kk = 1; kk < KK; ++kk) {
            float vv = fin[kk];
            if (vv > bv) { bv = vv; bk = kk; }
        }
        scur = bk;   // tag at t = T-1
    }
    __syncthreads();

    // ---------------- backward (serial, via shared reloads) ----------
    for (int base = NCH - GRP; base >= 0; base -= GRP) {
        // load 8 chunks' bp (32 KB, contiguous) into shared
        const uint4* src = (const uint4*)(bpb + (size_t)base * CHUNK * KK);
        uint4* dst = (uint4*)wb;
#pragma unroll
        for (int i = 0; i < (GRP * CHUNK * KK / 16) / 128; ++i)
            dst[tid + 128 * i] = src[tid + 128 * i];
        __syncthreads();

        if (tid == 0) {
            int cur = scur;  // tag at t = 64*(base+GRP) - 1
            for (int g = GRP - 1; g >= 0; --g) {
                tagseg[g * CHUNK + CHUNK - 1] = (float)cur;
                for (int r = CHUNK - 1; r >= 1; --r) {
                    cur = wb[g][r][cur];           // tag[t-1] = bp_t[tag_t]
                    tagseg[g * CHUNK + r - 1] = (float)cur;
                }
                cur = wb[g][0][cur];               // cross chunk boundary
            }
            scur = cur;
        }
        __syncthreads();

        // write 512 tags coalesced (FLOAT32 values)
        float* ob = out + (size_t)b * TT + base * CHUNK;
#pragma unroll
        for (int i = 0; i < (GRP * CHUNK) / 128; ++i)
            ob[tid + 128 * i] = tagseg[tid + 128 * i];
        __syncthreads();
    }

    // ---------------- sequence length ----------------
    {
        int s = 0;
        const int4* m = (const int4*)(mask + (size_t)b * TT);
        for (int i = tid; i < TT / 4; i += 128) {
            int4 v = m[i];
            s += v.x + v.y + v.z + v.w;
        }
#pragma unroll
        for (int off = 16; off; off >>= 1) s += __shfl_xor_sync(0xffffffffu, s, off);
        __shared__ int red[4];
        if ((tid & 31) == 0) red[tid >> 5] = s;
        __syncthreads();
        if (tid == 0)
            out[(size_t)BB * TT + b] = (float)(red[0] + red[1] + red[2] + red[3]);
    }
}

// =====================================================================
extern "C" void kernel_launch(void* const* d_in, const int* in_sizes, int n_in,
                              void* d_out, int out_size) {
    // identify inputs by element count (robust to metadata ordering)
    const float* pot   = nullptr;   // (128,4096,64) f32 -> 33554432
    const float* trans = nullptr;   // (64,64)       f32 -> 4096
    const int*   mask  = nullptr;   // (128,4096)    i32 -> 524288
    for (int i = 0; i < n_in; ++i) {
        if      (in_sizes[i] == BB * TT * KK) pot   = (const float*)d_in[i];
        else if (in_sizes[i] == KK * KK)      trans = (const float*)d_in[i];
        else if (in_sizes[i] == BB * TT)      mask  = (const int*)  d_in[i];
    }
    float* out = (float*)d_out;   // [tags (128*4096) | lengths (128)] as f32 values

    crf_kernel<<<BB, 128>>>(pot, trans, mask, out);
}

// round 6
// speedup vs baseline: 2.1319x; 2.1319x over previous
#include <cuda_runtime.h>
#include <cstdint>

#define BB 128
#define TT 4096
#define KK 64
#define CHUNK 64
#define NCH   (TT / CHUNK)   /* 64 chunks */
#define GRP   8              /* chunks walked per backward group (32 KB) */

// scratch: 32 MB backpointer store (static __device__: allocation-free)
__device__ __align__(16) uint8_t g_bp[(size_t)BB * TT * KK];

__device__ __forceinline__ void cpasync16(uint32_t saddr, const void* gptr) {
    asm volatile("cp.async.ca.shared.global [%0], [%1], 16;" :: "r"(saddr), "l"(gptr));
}
__device__ __forceinline__ void cpasync_commit() {
    asm volatile("cp.async.commit_group;");
}
__device__ __forceinline__ void cpasync_wait1() {
    asm volatile("cp.async.wait_group 1;");
}

// =====================================================================
// One CTA per batch. Forward Viterbi with cp.async-staged emissions and
// FMNMX+mask argmax; bp staged to global per 64-step chunk; then serial
// in-CTA backward via shared reloads; tags written as float32.
// 128 threads = 64 k-columns x 2 predecessor-halves.
// Exact fp32, first-index argmax (matches jnp.argmax).
// =====================================================================
__global__ __launch_bounds__(128) void crf_kernel(const float* __restrict__ pot,
                                                  const float* __restrict__ trans,
                                                  const int*   __restrict__ mask,
                                                  float*       __restrict__ out) {
    const int b   = blockIdx.x;
    const int tid = threadIdx.x;
    const int k   = tid >> 1;   // 0..63
    const int jh  = tid & 1;    // 0..1

    __shared__ __align__(16) float   st_s[2][KK];          // state double buffer
    __shared__ __align__(16) uint8_t bps[CHUNK][KK];       // bp staging (4 KB)
    __shared__ __align__(16) uint8_t buf32[32 * 1024];     // fwd: emission dbuf / bwd: walk buf
    __shared__ __align__(16) float   tagseg[GRP * CHUNK];  // 512 tags
    __shared__ int scur;

    float* const ebuf0 = (float*)buf32;                    // 16 KB each
    float* const ebuf1 = ebuf0 + CHUNK * KK;

    // transition slice in registers: tr[i] = transitions[32*jh + i][k]
    float tr[32];
#pragma unroll
    for (int i = 0; i < 32; ++i) tr[i] = trans[(jh * 32 + i) * KK + k];

    const float* pb  = pot + (size_t)b * TT * KK;
    uint8_t*     bpb = g_bp + (size_t)b * TT * KK;

    // ---- prologue: prefetch emission chunks 0 and 1 ----
    {
        uint32_t s0 = (uint32_t)__cvta_generic_to_shared(ebuf0);
        uint32_t s1 = (uint32_t)__cvta_generic_to_shared(ebuf1);
#pragma unroll
        for (int i = 0; i < 8; ++i)
            cpasync16(s0 + (i * 128 + tid) * 16, pb + (i * 128 + tid) * 4);
        cpasync_commit();
#pragma unroll
        for (int i = 0; i < 8; ++i)
            cpasync16(s1 + (i * 128 + tid) * 16, pb + (CHUNK * KK) + (i * 128 + tid) * 4);
        cpasync_commit();
        cpasync_wait1();          // chunk 0 ready
    }
    __syncthreads();

    if (jh == 0) {
        st_s[0][k] = ebuf0[k];    // alpha_0 = potentials[b,0,:]
        bps[0][k]  = (uint8_t)k;  // row-0 placeholder (never applied)
    }
    __syncthreads();

    // ---------------- forward ----------------
    for (int c = 0; c < NCH; ++c) {
        const float* eb = (c & 1) ? ebuf1 : ebuf0;
        const int r0 = (c == 0) ? 1 : 0;

        for (int r = r0; r < CHUNK; ++r) {
            const int t = c * CHUNK + r;
            const float* s = st_s[(t - 1) & 1] + jh * 32;

            float v[32];
#pragma unroll
            for (int i = 0; i < 8; ++i) {
                float4 s4 = ((const float4*)s)[i];
                v[4 * i + 0] = s4.x + tr[4 * i + 0];
                v[4 * i + 1] = s4.y + tr[4 * i + 1];
                v[4 * i + 2] = s4.z + tr[4 * i + 2];
                v[4 * i + 3] = s4.w + tr[4 * i + 3];
            }

            // max via FMNMX tree (no predicates)
            float m0 = fmaxf(v[0], v[1]),   m1 = fmaxf(v[2], v[3]);
            float m2 = fmaxf(v[4], v[5]),   m3 = fmaxf(v[6], v[7]);
            float m4 = fmaxf(v[8], v[9]),   m5 = fmaxf(v[10], v[11]);
            float m6 = fmaxf(v[12], v[13]), m7 = fmaxf(v[14], v[15]);
            float m8 = fmaxf(v[16], v[17]), m9 = fmaxf(v[18], v[19]);
            float ma = fmaxf(v[20], v[21]), mb = fmaxf(v[22], v[23]);
            float mc = fmaxf(v[24], v[25]), md = fmaxf(v[26], v[27]);
            float me = fmaxf(v[28], v[29]), mf = fmaxf(v[30], v[31]);
            m0 = fmaxf(m0, m1); m2 = fmaxf(m2, m3); m4 = fmaxf(m4, m5); m6 = fmaxf(m6, m7);
            m8 = fmaxf(m8, m9); ma = fmaxf(ma, mb); mc = fmaxf(mc, md); me = fmaxf(me, mf);
            m0 = fmaxf(m0, m2); m4 = fmaxf(m4, m6); m8 = fmaxf(m8, ma); mc = fmaxf(mc, me);
            m0 = fmaxf(m0, m4); m8 = fmaxf(m8, mc);
            const float vmax = fmaxf(m0, m8);

            // first-index argmax via equality mask (independent compares)
            unsigned msk = 0u;
#pragma unroll
            for (int i = 0; i < 32; ++i)
                msk |= (v[i] == vmax) ? (1u << i) : 0u;
            int gj_loc = jh * 32 + (__ffs(msk) - 1);

            // merge the two halves (adjacent lanes); first-index tie rule:
            // jh0's indices are all smaller, so jh0 yields only on strict '>'.
            float po = __shfl_xor_sync(0xffffffffu, vmax,   1);
            int   jo = __shfl_xor_sync(0xffffffffu, gj_loc, 1);
            float best = fmaxf(vmax, po);
            bool take = jh ? (po >= vmax) : (po > vmax);
            int gj = take ? jo : gj_loc;

            if (jh == 0) {
                st_s[t & 1][k] = best + eb[r * KK + k];   // emission from smem
                bps[r][k]      = (uint8_t)gj;
            }
            __syncthreads();
        }

        // ---- chunk boundary: flush bp, prefetch chunk c+2, sync chunk c+1 ----
        {
            uint4*       dst = (uint4*)(bpb + (size_t)c * CHUNK * KK);
            const uint4* src = (const uint4*)bps;
            dst[tid]       = src[tid];
            dst[tid + 128] = src[tid + 128];
        }
        if (c + 1 < NCH) {
            if (c + 2 < NCH) {
                // chunk c+2 has the same parity as chunk c -> reuse chunk c's
                // buffer (just consumed). (R5 bug: this was inverted.)
                float* enb = (c & 1) ? ebuf1 : ebuf0;
                uint32_t sn = (uint32_t)__cvta_generic_to_shared(enb);
                const float* gsrc = pb + (size_t)(c + 2) * CHUNK * KK;
#pragma unroll
                for (int i = 0; i < 8; ++i)
                    cpasync16(sn + (i * 128 + tid) * 16, gsrc + (i * 128 + tid) * 4);
            }
            cpasync_commit();
            cpasync_wait1();      // chunk c+1 ready (groups complete in order)
        }
        __syncthreads();
    }

    // ---------------- last tag ----------------
    if (tid == 0) {
        const float* fin = st_s[(TT - 1) & 1];
        float bv = fin[0]; int bk = 0;
#pragma unroll
        for (int kk = 1; kk < KK; ++kk) {
            float vv = fin[kk];
            if (vv > bv) { bv = vv; bk = kk; }
        }
        scur = bk;
    }
    __syncthreads();

    // ---------------- backward (serial walk via shared reloads) ----------
    typedef uint8_t (*WB)[CHUNK][KK];
    WB wb = (WB)buf32;                      // reuse the 32 KB buffer
    for (int base = NCH - GRP; base >= 0; base -= GRP) {
        const uint4* src = (const uint4*)(bpb + (size_t)base * CHUNK * KK);
        uint4* dst = (uint4*)buf32;
#pragma unroll
        for (int i = 0; i < (GRP * CHUNK * KK / 16) / 128; ++i)
            dst[tid + 128 * i] = src[tid + 128 * i];
        __syncthreads();

        if (tid == 0) {
            int cur = scur;                 // tag at t = 64*(base+GRP) - 1
            for (int g = GRP - 1; g >= 0; --g) {
                tagseg[g * CHUNK + CHUNK - 1] = (float)cur;
                for (int r = CHUNK - 1; r >= 1; --r) {
                    cur = wb[g][r][cur];
                    tagseg[g * CHUNK + r - 1] = (float)cur;
                }
                cur = wb[g][0][cur];        // cross chunk boundary
            }
            scur = cur;
        }
        __syncthreads();

        float* ob = out + (size_t)b * TT + base * CHUNK;
#pragma unroll
        for (int i = 0; i < (GRP * CHUNK) / 128; ++i)
            ob[tid + 128 * i] = tagseg[tid + 128 * i];
        __syncthreads();
    }

    // ---------------- sequence length ----------------
    {
        int s = 0;
        const int4* m = (const int4*)(mask + (size_t)b * TT);
        for (int i = tid; i < TT / 4; i += 128) {
            int4 v = m[i];
            s += v.x + v.y + v.z + v.w;
        }
#pragma unroll
        for (int off = 16; off; off >>= 1) s += __shfl_xor_sync(0xffffffffu, s, off);
        __shared__ int red[4];
        if ((tid & 31) == 0) red[tid >> 5] = s;
        __syncthreads();
        if (tid == 0)
            out[(size_t)BB * TT + b] = (float)(red[0] + red[1] + red[2] + red[3]);
    }
}

// =====================================================================
extern "C" void kernel_launch(void* const* d_in, const int* in_sizes, int n_in,
                              void* d_out, int out_size) {
    const float* pot   = nullptr;
    const float* trans = nullptr;
    const int*   mask  = nullptr;
    for (int i = 0; i < n_in; ++i) {
        if      (in_sizes[i] == BB * TT * KK) pot   = (const float*)d_in[i];
        else if (in_sizes[i] == KK * KK)      trans = (const float*)d_in[i];
        else if (in_sizes[i] == BB * TT)      mask  = (const int*)  d_in[i];
    }
    float* out = (float*)d_out;   // [tags (128*4096) | lengths (128)] as f32

    crf_kernel<<<BB, 128>>>(pot, trans, mask, out);
}